// round 2
// baseline (speedup 1.0000x reference)
#include <cuda_runtime.h>
#include <math.h>

#define BB 8
#define PP 15360
#define QQ 9216
#define HH 96
#define WW 96
#define NMODS 8
#define HALF 4608
#define HALF4 1152
#define RPC 32
#define BP_ROWS 320
#define BP_CHUNKS 48

// ---- scratch (static device globals; no allocation anywhere) ----
__device__ __align__(16) float g_sens_part[32 * QQ];
__device__ __align__(16) float g_inv_sens[QQ];
__device__ __align__(16) float g_img[BB * QQ];
__device__ __align__(16) float g_fp_part[2 * PP * 8];
__device__ __align__(16) float g_ratio[PP * 8];
__device__ __align__(16) float g_bp_part[BP_CHUNKS * BB * QQ];
__device__ __align__(16) float g_em[BB * QQ];
__device__ __align__(16) float g_hidden[BB * 32 * QQ];

// ---- sensitivity image: column sums of S ----
__global__ void k_sens_part(const float* __restrict__ S) {
    int q = blockIdx.x * 256 + threadIdx.x;
    int c = blockIdx.y;
    const float* base = S + (size_t)c * 480 * QQ + q;
    float s = 0.f;
    #pragma unroll 8
    for (int r = 0; r < 480; r++) s += base[(size_t)r * QQ];
    g_sens_part[c * QQ + q] = s;
}

__global__ void k_sens_fin() {
    int q = blockIdx.x * 256 + threadIdx.x;
    float s = 0.f;
    #pragma unroll
    for (int c = 0; c < 32; c++) s += g_sens_part[c * QQ + q];
    g_inv_sens[q] = (s != 0.f) ? 1.f / s : 0.f;
}

__global__ void k_init_img() {
    int n = blockIdx.x * 256 + threadIdx.x;
    g_img[n] = 1.f;
}

// ---- forward projection: fp[b,p] = sum_q img[b,q]*S[p,q] (half-q split) ----
__global__ __launch_bounds__(512, 1) void k_fp(const float* __restrict__ S) {
    extern __shared__ float s_img[];
    float4* s4 = (float4*)s_img;
    const int half = blockIdx.y;
    const int p0 = blockIdx.x * RPC;

    const float4* img4 = (const float4*)g_img;
    for (int j = threadIdx.x; j < 8 * HALF4; j += 512) {
        int b = j / HALF4;
        int i = j - b * HALF4;
        s4[j] = img4[b * 2304 + half * HALF4 + i];
    }
    __syncthreads();

    int warp = threadIdx.x >> 5, lane = threadIdx.x & 31;
    int pa = p0 + warp;
    int pb = p0 + warp + 16;
    const float4* rowA = (const float4*)(S + (size_t)pa * QQ + half * HALF);
    const float4* rowB = (const float4*)(S + (size_t)pb * QQ + half * HALF);

    float accA[8], accB[8];
    #pragma unroll
    for (int b = 0; b < 8; b++) { accA[b] = 0.f; accB[b] = 0.f; }

    #pragma unroll 2
    for (int i = lane; i < HALF4; i += 32) {
        float4 sa = rowA[i];
        float4 sb = rowB[i];
        #pragma unroll
        for (int b = 0; b < 8; b++) {
            float4 im = s4[b * HALF4 + i];
            accA[b] += sa.x * im.x + sa.y * im.y + sa.z * im.z + sa.w * im.w;
            accB[b] += sb.x * im.x + sb.y * im.y + sb.z * im.z + sb.w * im.w;
        }
    }

    #pragma unroll
    for (int b = 0; b < 8; b++) {
        #pragma unroll
        for (int off = 16; off > 0; off >>= 1) {
            accA[b] += __shfl_xor_sync(0xffffffffu, accA[b], off);
            accB[b] += __shfl_xor_sync(0xffffffffu, accB[b], off);
        }
    }
    if (lane == 0) {
        float* dA = g_fp_part + half * (PP * 8) + pa * 8;
        float* dB = g_fp_part + half * (PP * 8) + pb * 8;
        #pragma unroll
        for (int b = 0; b < 8; b++) { dA[b] = accA[b]; dB[b] = accB[b]; }
    }
}

// ---- ratio = where(fp>0, sino/fp, 0) ----
__global__ void k_ratio(const float* __restrict__ sino) {
    int n = blockIdx.x * 256 + threadIdx.x;  // n = p*8 + b
    int p = n >> 3, b = n & 7;
    float fp = g_fp_part[n] + g_fp_part[PP * 8 + n];
    float sv = sino[b * PP + p];
    g_ratio[n] = (fp > 0.f) ? sv / fp : 0.f;
}

// ---- backprojection partials: bp[b,q] = sum_p ratio[b,p]*S[p,q] ----
__global__ __launch_bounds__(256) void k_bp(const float* __restrict__ S) {
    __shared__ float s_ratio[BP_ROWS * 8];
    int cb = blockIdx.x;      // column block 0..8 (1024 cols each)
    int chunk = blockIdx.y;   // row chunk 0..47 (320 rows each)
    int p0 = chunk * BP_ROWS;

    for (int j = threadIdx.x; j < BP_ROWS * 8; j += 256)
        s_ratio[j] = g_ratio[p0 * 8 + j];
    __syncthreads();

    int qi = cb * 256 + threadIdx.x;  // float4 column index
    float4 acc[8];
    #pragma unroll
    for (int b = 0; b < 8; b++) acc[b] = make_float4(0.f, 0.f, 0.f, 0.f);

    #pragma unroll 2
    for (int r = 0; r < BP_ROWS; r++) {
        float4 s = ((const float4*)S)[(size_t)(p0 + r) * 2304 + qi];
        const float* rp = s_ratio + r * 8;
        #pragma unroll
        for (int b = 0; b < 8; b++) {
            float rv = rp[b];
            acc[b].x += rv * s.x; acc[b].y += rv * s.y;
            acc[b].z += rv * s.z; acc[b].w += rv * s.w;
        }
    }

    float4* bp4 = (float4*)g_bp_part;
    #pragma unroll
    for (int b = 0; b < 8; b++)
        bp4[(size_t)(chunk * 8 + b) * 2304 + qi] = acc[b];
}

// ---- reduce bp partials + EM image ----
__global__ void k_em() {
    int n = blockIdx.x * 256 + threadIdx.x;
    int q = n % QQ;
    float s = 0.f;
    #pragma unroll
    for (int c = 0; c < BP_CHUNKS; c++) s += g_bp_part[c * (BB * QQ) + n];
    g_em[n] = g_img[n] * g_inv_sens[q] * s;
}

// ---- conv1: 1->32 3x3 SAME + relu ----
__global__ __launch_bounds__(256) void k_conv1(const float* __restrict__ w1,
                                               const float* __restrict__ b1) {
    __shared__ float s_w[288];
    __shared__ float s_b[32];
    for (int j = threadIdx.x; j < 288; j += 256) s_w[j] = w1[j];
    if (threadIdx.x < 32) s_b[threadIdx.x] = b1[threadIdx.x];
    __syncthreads();

    int n = blockIdx.x * 256 + threadIdx.x;
    int b = n / QQ, rem = n % QQ;
    int y = rem / WW, x = rem % WW;

    float v[9];
    #pragma unroll
    for (int dy = 0; dy < 3; dy++)
        #pragma unroll
        for (int dx = 0; dx < 3; dx++) {
            int yy = y + dy - 1, xx = x + dx - 1;
            v[dy * 3 + dx] = (yy >= 0 && yy < HH && xx >= 0 && xx < WW)
                                 ? g_img[b * QQ + yy * WW + xx] : 0.f;
        }

    #pragma unroll 4
    for (int c = 0; c < 32; c++) {
        float a = s_b[c];
        #pragma unroll
        for (int k = 0; k < 9; k++) a += v[k] * s_w[c * 9 + k];
        g_hidden[(b * 32 + c) * QQ + rem] = fmaxf(a, 0.f);
    }
}

// ---- conv2 (32->1 3x3 SAME) fused with FBSEM fusion ----
__global__ __launch_bounds__(256) void k_conv2f(const float* __restrict__ w2,
                                                const float* __restrict__ b2,
                                                const float* __restrict__ beta,
                                                float* __restrict__ out,
                                                int write_out) {
    __shared__ float s_w[288];
    __shared__ float s_h[10 * 100];
    int b = blockIdx.x / 12, strip = blockIdx.x % 12;
    int y0 = strip * 8;

    for (int j = threadIdx.x; j < 288; j += 256) s_w[j] = w2[j];
    float bias = b2[0];
    float bt = beta[0];

    int py[3], px[3];
    #pragma unroll
    for (int j = 0; j < 3; j++) {
        int pid = threadIdx.x + j * 256;  // 0..767 pixels in strip
        py[j] = pid / 96;
        px[j] = pid % 96;
    }
    float acc[3] = {bias, bias, bias};

    for (int c = 0; c < 32; c++) {
        __syncthreads();
        const float* hsrc = g_hidden + (size_t)(b * 32 + c) * QQ;
        for (int j = threadIdx.x; j < 980; j += 256) {
            int ty = j / 98, tx = j % 98;
            int yy = y0 - 1 + ty, xx = tx - 1;
            s_h[ty * 100 + tx] = (yy >= 0 && yy < HH && xx >= 0 && xx < WW)
                                     ? hsrc[yy * WW + xx] : 0.f;
        }
        __syncthreads();
        const float* wc = s_w + c * 9;
        #pragma unroll
        for (int j = 0; j < 3; j++) {
            float a = 0.f;
            #pragma unroll
            for (int dy = 0; dy < 3; dy++)
                #pragma unroll
                for (int dx = 0; dx < 3; dx++)
                    a += s_h[(py[j] + dy) * 100 + px[j] + dx] * wc[dy * 3 + dx];
            acc[j] += a;
        }
    }

    #pragma unroll
    for (int j = 0; j < 3; j++) {
        int yy = y0 + py[j];
        int q = yy * WW + px[j];
        int n = b * QQ + q;
        float inv = g_inv_sens[q];
        float b2i = bt * bt * inv;
        float em = g_em[n];
        float t = 1.f - b2i * acc[j];
        float val = 2.f * em / (t + sqrtf(t * t + 4.f * b2i * em));
        g_img[n] = val;
        if (write_out) out[n] = val;
    }
}

extern "C" void kernel_launch(void* const* d_in, const int* in_sizes, int n_in,
                              void* d_out, int out_size) {
    const float* sino = (const float*)d_in[0];
    const float* S    = (const float*)d_in[1];
    const float* w1   = (const float*)d_in[2];
    const float* b1   = (const float*)d_in[3];
    const float* w2   = (const float*)d_in[4];
    const float* b2   = (const float*)d_in[5];
    const float* beta = (const float*)d_in[6];
    float* out = (float*)d_out;

    cudaFuncSetAttribute(k_fp, cudaFuncAttributeMaxDynamicSharedMemorySize,
                         8 * HALF * (int)sizeof(float));

    k_sens_part<<<dim3(36, 32), 256>>>(S);
    k_sens_fin<<<36, 256>>>();
    k_init_img<<<288, 256>>>();

    for (int it = 0; it < NMODS; it++) {
        k_fp<<<dim3(PP / RPC, 2), 512, 8 * HALF * (int)sizeof(float)>>>(S);
        k_ratio<<<480, 256>>>(sino);
        k_bp<<<dim3(9, BP_CHUNKS), 256>>>(S);
        k_em<<<288, 256>>>();
        k_conv1<<<288, 256>>>(w1, b1);
        k_conv2f<<<96, 256>>>(w2, b2, beta, out, (it == NMODS - 1) ? 1 : 0);
    }
}